// round 10
// baseline (speedup 1.0000x reference)
#include <cuda_runtime.h>
#include <cstdint>

// GaussianVoxelizer: 2M gaussians -> 640K voxels argmax-by-opacity (min-index
// tiebreak), then per-voxel gather + analytic covariance inverse.
//
// ROUND-9 STRUCTURE (78.0us) with ONE delta: init kernel removed, and the
// output kernel resets g_keys[g]=0 after reading it (zero-invariant across
// graph replays; device globals are zero-initialized at module load).
// Scalar rots loads kept (bisect: every regs=48 / 89us output build had the
// float4 rots load; round 9 with scalar rots was back to ~60us output).
//
// CODEGEN-CRITICAL: gather destinations are elements of one r[31] local
// array copied to smem only at the end -> all gather LDGs stay live ->
// full MLP. Do not restructure (rounds 4-7 regressions).
//
// Voxel binning matches XLA's lowering of (x - vol_min) / 0.4: divide by
// constant folds to multiply by reciprocal; 1/0.4f == 2.5f exactly.

namespace {
constexpr int kH = 200, kW = 200, kD = 16;
constexpr int kV = kH * kW * kD;   // 640000
constexpr int kRow = 31;
constexpr int kBlk = 256;
}

__device__ unsigned long long g_keys[kV];   // zero-initialized at module load

__global__ void gv_scatter_kernel(const float* __restrict__ means,
                                  const float* __restrict__ opac,
                                  int n) {
    int i = blockIdx.x * blockDim.x + threadIdx.x;
    if (i >= n) return;
    float x = means[3 * i + 0];
    float y = means[3 * i + 1];
    float z = means[3 * i + 2];
    // Match XLA: (p - VOL_MIN) * (1/VOX) with 1/0.4f == 2.5f, round-half-even.
    int vx = __float2int_rn(__fmul_rn(__fadd_rn(x, 40.0f), 2.5f));
    int vy = __float2int_rn(__fmul_rn(__fadd_rn(y, 40.0f), 2.5f));
    int vz = __float2int_rn(__fmul_rn(__fadd_rn(z, 1.0f), 2.5f));
    vx = min(max(vx, 0), kH - 1);
    vy = min(max(vy, 0), kW - 1);
    vz = min(max(vz, 0), kD - 1);
    int flat = vx * (kW * kD) + vy * kD + vz;
    float o = opac[i];
    // opacity in [0,1) -> non-negative float, bit pattern is order-preserving.
    unsigned long long key =
        ((unsigned long long)__float_as_uint(o) << 32) |
        (unsigned long long)(0xFFFFFFFFu - (unsigned)i);
    atomicMax(&g_keys[flat], key);
}

__global__ void __launch_bounds__(kBlk)
gv_output_kernel(const float* __restrict__ means,
                 const float* __restrict__ opac,
                 const float* __restrict__ feats,
                 const float* __restrict__ scales,
                 const float* __restrict__ rots,
                 const float* __restrict__ empty_scalar,
                 float* __restrict__ out) {
    __shared__ float srows[kBlk * kRow];

    int tid = threadIdx.x;
    int g = blockIdx.x * kBlk + tid;

    if (g <= kV) {
        float r[kRow];
#pragma unroll
        for (int c = 0; c < kRow; c++) r[c] = 0.0f;

        float sx = 1.0f, sy = 1.0f, sz = 1.0f;
        float qw = 1.0f, qx = 0.0f, qy = 0.0f, qz = 0.0f;

        if (g == kV) {
            // appended "empty" gaussian row
            r[0] = 0.0f; r[1] = 0.0f; r[2] = 2.2f;
            r[3] = 1.0f;                       // opacity
            r[4 + 17] = empty_scalar[0];       // EMPTY_LABEL semantic
            sx = 100.0f; sy = 100.0f; sz = 8.0f;
        } else {
            unsigned long long key = g_keys[g];
            g_keys[g] = 0ull;   // restore zero-invariant for next replay
            if (key != 0ull) {
                int idx = (int)(0xFFFFFFFFu - (unsigned)(key & 0xFFFFFFFFull));
                r[0] = means[3 * idx + 0];
                r[1] = means[3 * idx + 1];
                r[2] = means[3 * idx + 2];
                r[3] = opac[idx];
#pragma unroll
                for (int c = 0; c < 17; c++) r[4 + c] = feats[17 * idx + c];
                sx = scales[3 * idx + 0];
                sy = scales[3 * idx + 1];
                sz = scales[3 * idx + 2];
                qw = rots[4 * idx + 0];
                qx = rots[4 * idx + 1];
                qy = rots[4 * idx + 2];
                qz = rots[4 * idx + 3];
            }
            // invalid voxel: defaults -> covinv = I, rest 0 (matches ref).
        }

        float nrm = sqrtf(qw * qw + qx * qx + qy * qy + qz * qz);
        float inv = 1.0f / nrm;
        qw *= inv; qx *= inv; qy *= inv; qz *= inv;

        float r00 = 1.0f - 2.0f * (qy * qy + qz * qz);
        float r01 = 2.0f * (qx * qy - qw * qz);
        float r02 = 2.0f * (qx * qz + qw * qy);
        float r10 = 2.0f * (qx * qy + qw * qz);
        float r11 = 1.0f - 2.0f * (qx * qx + qz * qz);
        float r12 = 2.0f * (qy * qz - qw * qx);
        float r20 = 2.0f * (qx * qz - qw * qy);
        float r21 = 2.0f * (qy * qz + qw * qx);
        float r22 = 1.0f - 2.0f * (qx * qx + qy * qy);

        // cov = R^T S^2 R  =>  cov_inv = R^T S^-2 R (analytic, symmetric)
        float a0 = 1.0f / (sx * sx);
        float a1 = 1.0f / (sy * sy);
        float a2 = 1.0f / (sz * sz);

        float c00 = r00 * r00 * a0 + r10 * r10 * a1 + r20 * r20 * a2;
        float c01 = r00 * r01 * a0 + r10 * r11 * a1 + r20 * r21 * a2;
        float c02 = r00 * r02 * a0 + r10 * r12 * a1 + r20 * r22 * a2;
        float c11 = r01 * r01 * a0 + r11 * r11 * a1 + r21 * r21 * a2;
        float c12 = r01 * r02 * a0 + r11 * r12 * a1 + r21 * r22 * a2;
        float c22 = r02 * r02 * a0 + r12 * r12 * a1 + r22 * r22 * a2;

        r[22] = c00; r[23] = c01; r[24] = c02;
        r[25] = c01; r[26] = c11; r[27] = c12;
        r[28] = c02; r[29] = c12; r[30] = c22;

        // stage row in smem: address tid*31 + c, stride 31 mod 32 -> no
        // bank conflicts across the warp for any fixed c.
#pragma unroll
        for (int c = 0; c < kRow; c++) srows[tid * kRow + c] = r[c];
    }

    __syncthreads();

    // coalesced writeback: full blocks cover a contiguous span of
    // kBlk*31 floats, 16B-aligned -> float4 path.
    int base = blockIdx.x * kBlk;
    int nrows = min(kBlk, kV + 1 - base);
    if (nrows <= 0) return;

    if (nrows == kBlk) {
        constexpr int kVec = kBlk * kRow / 4;   // 1984 float4s
        float4* po = reinterpret_cast<float4*>(out + (size_t)base * kRow);
        const float4* ps = reinterpret_cast<const float4*>(srows);
        for (int e = tid; e < kVec; e += kBlk) {
            po[e] = ps[e];
        }
    } else {
        int nelem = nrows * kRow;
        float* po = out + (size_t)base * kRow;
        for (int e = tid; e < nelem; e += kBlk) {
            po[e] = srows[e];
        }
    }
}

extern "C" void kernel_launch(void* const* d_in, const int* in_sizes, int n_in,
                              void* d_out, int out_size) {
    const float* means        = (const float*)d_in[0];  // [N,3]
    const float* opac         = (const float*)d_in[1];  // [N,1]
    const float* feats        = (const float*)d_in[2];  // [N,17]
    const float* scales       = (const float*)d_in[3];  // [N,3]
    const float* rots         = (const float*)d_in[4];  // [N,4]
    const float* empty_scalar = (const float*)d_in[5];  // [1]
    float* out = (float*)d_out;                         // [1, V+1, 31]

    int n = in_sizes[0] / 3;

    gv_scatter_kernel<<<(n + 255) / 256, 256>>>(means, opac, n);
    gv_output_kernel<<<(kV + 1 + kBlk - 1) / kBlk, kBlk>>>(
        means, opac, feats, scales, rots, empty_scalar, out);
}

// round 11
// speedup vs baseline: 1.3136x; 1.3136x over previous
#include <cuda_runtime.h>
#include <cstdint>

// GaussianVoxelizer: 2M gaussians -> 640K voxels argmax-by-opacity (min-index
// tiebreak), then per-voxel gather + analytic covariance inverse.
//
// ROUND-9 GATHER BODY, byte-identical (78.0us), + init-kernel deletion:
// g_keys[g]=0 reset moved to the VERY END of the output kernel (after
// __syncthreads + writeback). Bisect evidence:
//   - reset store between key-load and gather batch  -> regs 47, output 90us
//     (the store acts as a scheduling fence; ptxas stops hoisting the
//      21-LDG gather batch, MLP collapses)
//   - no reset (round 9)                             -> output ~60us
// Moving the reset after the barrier keeps the hot path untouched while
// preserving the zero-invariant across graph replays (device globals are
// zero-initialized at module load; every replay re-zeroes what it read).
//
// CODEGEN-CRITICAL: gather destinations are elements of one r[31] local
// array copied to smem only at the end -> all gather LDGs stay live ->
// full MLP. Scalar rots loads. Do not restructure (rounds 4-8 regressions).
//
// Voxel binning matches XLA's lowering of (x - vol_min) / 0.4: divide by
// constant folds to multiply by reciprocal; 1/0.4f == 2.5f exactly.

namespace {
constexpr int kH = 200, kW = 200, kD = 16;
constexpr int kV = kH * kW * kD;   // 640000
constexpr int kRow = 31;
constexpr int kBlk = 256;
}

__device__ unsigned long long g_keys[kV];   // zero-initialized at module load

__global__ void gv_scatter_kernel(const float* __restrict__ means,
                                  const float* __restrict__ opac,
                                  int n) {
    int i = blockIdx.x * blockDim.x + threadIdx.x;
    if (i >= n) return;
    float x = means[3 * i + 0];
    float y = means[3 * i + 1];
    float z = means[3 * i + 2];
    // Match XLA: (p - VOL_MIN) * (1/VOX) with 1/0.4f == 2.5f, round-half-even.
    int vx = __float2int_rn(__fmul_rn(__fadd_rn(x, 40.0f), 2.5f));
    int vy = __float2int_rn(__fmul_rn(__fadd_rn(y, 40.0f), 2.5f));
    int vz = __float2int_rn(__fmul_rn(__fadd_rn(z, 1.0f), 2.5f));
    vx = min(max(vx, 0), kH - 1);
    vy = min(max(vy, 0), kW - 1);
    vz = min(max(vz, 0), kD - 1);
    int flat = vx * (kW * kD) + vy * kD + vz;
    float o = opac[i];
    // opacity in [0,1) -> non-negative float, bit pattern is order-preserving.
    unsigned long long key =
        ((unsigned long long)__float_as_uint(o) << 32) |
        (unsigned long long)(0xFFFFFFFFu - (unsigned)i);
    atomicMax(&g_keys[flat], key);
}

__global__ void __launch_bounds__(kBlk)
gv_output_kernel(const float* __restrict__ means,
                 const float* __restrict__ opac,
                 const float* __restrict__ feats,
                 const float* __restrict__ scales,
                 const float* __restrict__ rots,
                 const float* __restrict__ empty_scalar,
                 float* __restrict__ out) {
    __shared__ float srows[kBlk * kRow];

    int tid = threadIdx.x;
    int g = blockIdx.x * kBlk + tid;

    if (g <= kV) {
        float r[kRow];
#pragma unroll
        for (int c = 0; c < kRow; c++) r[c] = 0.0f;

        float sx = 1.0f, sy = 1.0f, sz = 1.0f;
        float qw = 1.0f, qx = 0.0f, qy = 0.0f, qz = 0.0f;

        if (g == kV) {
            // appended "empty" gaussian row
            r[0] = 0.0f; r[1] = 0.0f; r[2] = 2.2f;
            r[3] = 1.0f;                       // opacity
            r[4 + 17] = empty_scalar[0];       // EMPTY_LABEL semantic
            sx = 100.0f; sy = 100.0f; sz = 8.0f;
        } else {
            unsigned long long key = g_keys[g];
            if (key != 0ull) {
                int idx = (int)(0xFFFFFFFFu - (unsigned)(key & 0xFFFFFFFFull));
                r[0] = means[3 * idx + 0];
                r[1] = means[3 * idx + 1];
                r[2] = means[3 * idx + 2];
                r[3] = opac[idx];
#pragma unroll
                for (int c = 0; c < 17; c++) r[4 + c] = feats[17 * idx + c];
                sx = scales[3 * idx + 0];
                sy = scales[3 * idx + 1];
                sz = scales[3 * idx + 2];
                qw = rots[4 * idx + 0];
                qx = rots[4 * idx + 1];
                qy = rots[4 * idx + 2];
                qz = rots[4 * idx + 3];
            }
            // invalid voxel: defaults -> covinv = I, rest 0 (matches ref).
        }

        float nrm = sqrtf(qw * qw + qx * qx + qy * qy + qz * qz);
        float inv = 1.0f / nrm;
        qw *= inv; qx *= inv; qy *= inv; qz *= inv;

        float r00 = 1.0f - 2.0f * (qy * qy + qz * qz);
        float r01 = 2.0f * (qx * qy - qw * qz);
        float r02 = 2.0f * (qx * qz + qw * qy);
        float r10 = 2.0f * (qx * qy + qw * qz);
        float r11 = 1.0f - 2.0f * (qx * qx + qz * qz);
        float r12 = 2.0f * (qy * qz - qw * qx);
        float r20 = 2.0f * (qx * qz - qw * qy);
        float r21 = 2.0f * (qy * qz + qw * qx);
        float r22 = 1.0f - 2.0f * (qx * qx + qy * qy);

        // cov = R^T S^2 R  =>  cov_inv = R^T S^-2 R (analytic, symmetric)
        float a0 = 1.0f / (sx * sx);
        float a1 = 1.0f / (sy * sy);
        float a2 = 1.0f / (sz * sz);

        float c00 = r00 * r00 * a0 + r10 * r10 * a1 + r20 * r20 * a2;
        float c01 = r00 * r01 * a0 + r10 * r11 * a1 + r20 * r21 * a2;
        float c02 = r00 * r02 * a0 + r10 * r12 * a1 + r20 * r22 * a2;
        float c11 = r01 * r01 * a0 + r11 * r11 * a1 + r21 * r21 * a2;
        float c12 = r01 * r02 * a0 + r11 * r12 * a1 + r21 * r22 * a2;
        float c22 = r02 * r02 * a0 + r12 * r12 * a1 + r22 * r22 * a2;

        r[22] = c00; r[23] = c01; r[24] = c02;
        r[25] = c01; r[26] = c11; r[27] = c12;
        r[28] = c02; r[29] = c12; r[30] = c22;

        // stage row in smem: address tid*31 + c, stride 31 mod 32 -> no
        // bank conflicts across the warp for any fixed c.
#pragma unroll
        for (int c = 0; c < kRow; c++) srows[tid * kRow + c] = r[c];
    }

    __syncthreads();

    // coalesced writeback: full blocks cover a contiguous span of
    // kBlk*31 floats, 16B-aligned -> float4 path.
    int base = blockIdx.x * kBlk;
    int nrows = min(kBlk, kV + 1 - base);
    if (nrows > 0) {
        if (nrows == kBlk) {
            constexpr int kVec = kBlk * kRow / 4;   // 1984 float4s
            float4* po = reinterpret_cast<float4*>(out + (size_t)base * kRow);
            const float4* ps = reinterpret_cast<const float4*>(srows);
            for (int e = tid; e < kVec; e += kBlk) {
                po[e] = ps[e];
            }
        } else {
            int nelem = nrows * kRow;
            float* po = out + (size_t)base * kRow;
            for (int e = tid; e < nelem; e += kBlk) {
                po[e] = srows[e];
            }
        }
    }

    // reset AFTER the hot path (post-barrier, post-writeback): restores the
    // zero-invariant for the next graph replay without perturbing the
    // gather codegen above.
    if (g < kV) g_keys[g] = 0ull;
}

extern "C" void kernel_launch(void* const* d_in, const int* in_sizes, int n_in,
                              void* d_out, int out_size) {
    const float* means        = (const float*)d_in[0];  // [N,3]
    const float* opac         = (const float*)d_in[1];  // [N,1]
    const float* feats        = (const float*)d_in[2];  // [N,17]
    const float* scales       = (const float*)d_in[3];  // [N,3]
    const float* rots         = (const float*)d_in[4];  // [N,4]
    const float* empty_scalar = (const float*)d_in[5];  // [1]
    float* out = (float*)d_out;                         // [1, V+1, 31]

    int n = in_sizes[0] / 3;

    gv_scatter_kernel<<<(n + 255) / 256, 256>>>(means, opac, n);
    gv_output_kernel<<<(kV + 1 + kBlk - 1) / kBlk, kBlk>>>(
        means, opac, feats, scales, rots, empty_scalar, out);
}